// round 6
// baseline (speedup 1.0000x reference)
#include <cuda_runtime.h>
#include <cuda_bf16.h>
#include <math.h>

#define Hh   8
#define Dm   128
#define Ee   128
#define KDk  16
#define Bb   16
#define NPICK 250
#define NDEL  250
#define Gg   501            // 1 + NPICK + NDEL
#define NTOK (Bb*Gg)        // 8016
#define GPAD 512            // padded row length for g_heads2

typedef unsigned long long u64;

// ---------------- packed f32x2 helpers (FFMA2 path, 2x fp32 rate) ----------
__device__ __forceinline__ u64 fma2(u64 a, u64 b, u64 c) {
    u64 d; asm("fma.rn.f32x2 %0, %1, %2, %3;" : "=l"(d) : "l"(a), "l"(b), "l"(c));
    return d;
}
__device__ __forceinline__ u64 mul2(u64 a, u64 b) {
    u64 d; asm("mul.rn.f32x2 %0, %1, %2;" : "=l"(d) : "l"(a), "l"(b));
    return d;
}
__device__ __forceinline__ u64 add2(u64 a, u64 b) {
    u64 d; asm("add.rn.f32x2 %0, %1, %2;" : "=l"(d) : "l"(a), "l"(b));
    return d;
}
__device__ __forceinline__ void upk(u64 a, float& x, float& y) {
    asm("mov.b64 {%0, %1}, %2;" : "=f"(x), "=f"(y) : "l"(a));
}
__device__ __forceinline__ u64 dup2(float x) {
    u64 r; asm("mov.b64 %0, {%1, %1};" : "=l"(r) : "f"(x));
    return r;
}
__device__ __forceinline__ float ex2f(float x) {
    float r; asm("ex2.approx.ftz.f32 %0, %1;" : "=f"(r) : "f"(x));
    return r;
}

union F4 { float4 v; u64 p[2]; };

// ---------------- device scratch ----------------
#define WPAD 132
__device__ float g_Wt[Hh*7*KDk*WPAD];       // transposed+padded weights
__device__ float g_K [Hh*Bb*Gg*KDk];
__device__ float g_V [Hh*Bb*Gg*KDk];
__device__ float g_Qm[Hh*Bb*Gg*KDk];        // pre-scaled by nf*log2(e)
__device__ float g_QA[Hh*Bb*Gg*KDk];
__device__ float g_QB[Hh*Bb*Gg*KDk];
__device__ float g_heads2[Bb*128*GPAD];     // [b][h*16+v][g] hv-major, rows padded

#define SCL   (0.25f * 1.44269504f)    // 1/sqrt(KD) * log2(e)
#define M2OFF 16.0f                    // fixed softmax offset (log2 units)

// ==========================================================================
// Kernel 0: weight prep.  g_Wt[h][m*16+k][d] = W_m[h][d][k]  (row pad 132)
// ==========================================================================
__global__ void wprep_kernel(const float* __restrict__ Wq, const float* __restrict__ Wk,
                             const float* __restrict__ Wv, const float* __restrict__ W1,
                             const float* __restrict__ W2, const float* __restrict__ W3,
                             const float* __restrict__ W4)
{
    const float* Ws[7] = {Wq, Wk, Wv, W1, W2, W3, W4};
    const int m = blockIdx.x, h = blockIdx.y;
    const float* w = Ws[m] + h * (Dm*KDk);
    float* dst = g_Wt + (size_t)(h*7*KDk + m*KDk) * WPAD;
    for (int idx = threadIdx.x; idx < Dm*KDk; idx += 256) {
        int d = idx >> 4, k = idx & 15;
        dst[k*WPAD + d] = w[idx];
    }
}

// ==========================================================================
// Kernel 1: projections.  Block = (80-token chunk, head), 256 threads.
// thread (k = tid&15, tg = tid>>4): 5 tokens x 7 mats, fma2 inner loop.
// rows padded to 132 floats (float4-aligned) -> LDS.128 loads.
// ==========================================================================
#define PT_TOK 80
#define QPAD   132
#define K1_SMEM ((7*16*WPAD + PT_TOK*QPAD)*4)   // 101376 B

__global__ void __launch_bounds__(256) proj_kernel(const float* __restrict__ q)
{
    extern __shared__ float sm[];
    float* Wt = sm;                         // 112*132
    float* qs = sm + 7*KDk*WPAD;            // 80*132

    const int h    = blockIdx.y;
    const int base = blockIdx.x * PT_TOK;
    const int tid  = threadIdx.x;
    const int nTok = min(PT_TOK, NTOK - base);

    {   // stage padded weights (contiguous float2 copy, L2-hot)
        const float2* src = (const float2*)(g_Wt + (size_t)h*7*KDk*WPAD);
        float2*       dst = (float2*)Wt;
#pragma unroll
        for (int i = 0; i < 29; i++) {      // 29*256 = 7424 >= 7392
            int idx = tid + i*256;
            if (idx < 7*KDk*WPAD/2) dst[idx] = src[idx];
        }
    }
    {   // stage q rows with padding (float4 granularity)
        const float4* qg = (const float4*)(q + (size_t)base * Dm);
        const int n4 = nTok * (Dm/4);
        for (int idx = tid; idx < n4; idx += 256) {
            int t = idx >> 5, i = idx & 31;
            ((float4*)(qs + t*QPAD))[i] = qg[idx];
        }
    }
    __syncthreads();

    const int k  = tid & 15;
    const int tg = tid >> 4;                // 16 groups x 5 tokens
    const int t0 = tg * 5;

    u64 acc[5][7];
#pragma unroll
    for (int i = 0; i < 5; i++)
#pragma unroll
        for (int m = 0; m < 7; m++) acc[i][m] = 0ull;

    const float4* qr[5];
#pragma unroll
    for (int i = 0; i < 5; i++) qr[i] = (const float4*)(qs + (t0 + i)*QPAD);
    const float4* wr[7];
#pragma unroll
    for (int m = 0; m < 7; m++) wr[m] = (const float4*)(Wt + (m*16 + k)*WPAD);

#pragma unroll 2
    for (int d4 = 0; d4 < Dm/4; d4++) {
        F4 qv[5];
#pragma unroll
        for (int i = 0; i < 5; i++) qv[i].v = qr[i][d4];
#pragma unroll
        for (int m = 0; m < 7; m++) {
            F4 w; w.v = wr[m][d4];
#pragma unroll
            for (int i = 0; i < 5; i++) {
                acc[i][m] = fma2(qv[i].p[0], w.p[0], acc[i][m]);
                acc[i][m] = fma2(qv[i].p[1], w.p[1], acc[i][m]);
            }
        }
    }

#pragma unroll
    for (int i = 0; i < 5; i++) {
        if (t0 + i >= nTok) break;
        float s[7];
#pragma unroll
        for (int m = 0; m < 7; m++) { float x, y; upk(acc[i][m], x, y); s[m] = x + y; }
        const int token = base + t0 + i;
        const int b = token / Gg;
        const int g = token - b * Gg;
        const bool pick = (g >= 1 && g <= NPICK);
        const int idx = ((h*Bb + b)*Gg + g)*KDk + k;
        g_Qm[idx] = s[0] * SCL;
        g_K [idx] = s[1];
        g_V [idx] = s[2];
        g_QA[idx] = (pick ? s[3] : s[5]) * SCL;
        g_QB[idx] = (pick ? s[4] : s[6]) * SCL;
    }
}

// ==========================================================================
// Kernel 2: fused attention.  One block per (h,b), 512 threads, one q-row
// per thread.  Fixed-offset exp2 softmax; K/V rows loaded as float4
// (LDS.128 broadcast) and bit-cast to u64 pairs for fma2.
// ==========================================================================
#define K2_SMEM (2*Gg*KDk*4)   // 64128 B

__device__ __forceinline__ float score16(const u64* qm, const float4* kr4)
{
    F4 k0, k1, k2, k3;
    k0.v = kr4[0]; k1.v = kr4[1]; k2.v = kr4[2]; k3.v = kr4[3];
    u64 a0 = mul2(qm[0], k0.p[0]);
    u64 a1 = mul2(qm[1], k0.p[1]);
    a0 = fma2(qm[2], k1.p[0], a0);
    a1 = fma2(qm[3], k1.p[1], a1);
    a0 = fma2(qm[4], k2.p[0], a0);
    a1 = fma2(qm[5], k2.p[1], a1);
    a0 = fma2(qm[6], k3.p[0], a0);
    a1 = fma2(qm[7], k3.p[1], a1);
    a0 = add2(a0, a1);
    float x, y; upk(a0, x, y);
    return x + y;
}

__device__ __forceinline__ void accum16(u64 pp, const float4* vr4, u64* o)
{
    F4 v0, v1, v2, v3;
    v0.v = vr4[0]; v1.v = vr4[1]; v2.v = vr4[2]; v3.v = vr4[3];
    o[0] = fma2(pp, v0.p[0], o[0]);
    o[1] = fma2(pp, v0.p[1], o[1]);
    o[2] = fma2(pp, v1.p[0], o[2]);
    o[3] = fma2(pp, v1.p[1], o[3]);
    o[4] = fma2(pp, v2.p[0], o[4]);
    o[5] = fma2(pp, v2.p[1], o[5]);
    o[6] = fma2(pp, v3.p[0], o[6]);
    o[7] = fma2(pp, v3.p[1], o[7]);
}

__global__ void __launch_bounds__(512) attn_kernel()
{
    extern __shared__ float sm[];

    const int b  = blockIdx.x;
    const int h  = blockIdx.y;
    const int tid = threadIdx.x;
    const int hb  = h*Bb + b;

    {   // stage K,V for this (h,b): 501 x 16 floats each
        const float4* Kg = (const float4*)(g_K + (size_t)hb * Gg * KDk);
        const float4* Vg = (const float4*)(g_V + (size_t)hb * Gg * KDk);
        float4* Ks4 = (float4*)sm;
        float4* Vs4 = (float4*)(sm + Gg*KDk);
        for (int i = tid; i < Gg*4; i += 512) { Ks4[i] = Kg[i]; Vs4[i] = Vg[i]; }
    }
    __syncthreads();

    const int qrow = tid;
    if (qrow >= Gg) return;

    const float4* Ks = (const float4*)sm;
    const float4* Vs = Ks + Gg*4;

    const int qidx = (hb*Gg + qrow)*KDk;
    u64 qm[8];
    {
        const u64* qp = (const u64*)(g_Qm + qidx);
#pragma unroll
        for (int j = 0; j < 8; j++) qm[j] = qp[j];
    }

    float l = 0.f;
    u64 o[8];
#pragma unroll
    for (int j = 0; j < 8; j++) o[j] = 0ull;

    // ---- main block: 501 keys, no mask ----
#pragma unroll 4
    for (int g = 0; g < Gg; g++) {
        float s = score16(qm, Ks + g*4);
        float p = ex2f(s - M2OFF);
        l += p;
        accum16(dup2(p), Vs + g*4, o);
    }

    // ---- extra blocks (rows 1..500 only), zmask: score==0 -> excluded ----
    if (qrow >= 1) {
        u64 qa[8], qb[8];
        {
            const u64* pa = (const u64*)(g_QA + qidx);
            const u64* pb = (const u64*)(g_QB + qidx);
#pragma unroll
            for (int j = 0; j < 8; j++) { qa[j] = pa[j]; qb[j] = pb[j]; }
        }
        const float4* Kp = Ks + 1*4;
        const float4* Vp = Vs + 1*4;
#pragma unroll 4
        for (int g = 0; g < NPICK; g++) {
            float s = score16(qa, Kp + g*4);
            float p = ex2f(s - M2OFF);
            p = (s == 0.f) ? 0.f : p;
            l += p;
            accum16(dup2(p), Vp + g*4, o);
        }
        const float4* Kd = Ks + (1+NPICK)*4;
        const float4* Vd = Vs + (1+NPICK)*4;
#pragma unroll 4
        for (int g = 0; g < NDEL; g++) {
            float s = score16(qb, Kd + g*4);
            float p = ex2f(s - M2OFF);
            p = (s == 0.f) ? 0.f : p;
            l += p;
            accum16(dup2(p), Vd + g*4, o);
        }
    }

    const float inv = 1.f / l;
    const u64 iv = dup2(inv);
    // hv-major write: g_heads2[b][h*16+v][qrow]
    float* hp = g_heads2 + ((size_t)b*128 + h*16)*GPAD + qrow;
#pragma unroll
    for (int j = 0; j < 8; j++) {
        float x, y; upk(mul2(o[j], iv), x, y);
        hp[(2*j  )*GPAD] = x;
        hp[(2*j+1)*GPAD] = y;
    }
}

// ==========================================================================
// Kernel 3: out[b,g,e] = sum_hv heads2[b][hv][g] * W_out[hv][e]
// Register-tiled GEMM.  Block = (64-token g-tile, b), 256 threads, 1 blk/SM.
// Thread (elane, grow) computes 4g x 8e via 16 u64 fma2 accumulators.
// ==========================================================================
#define OT_GT  64
#define A_PAD  68      // float4-aligned
#define W_PAD  130
#define K3_SMEM ((128*W_PAD + 128*A_PAD)*4)   // 101376 B

__global__ void __launch_bounds__(256) out_kernel(const float* __restrict__ Wo,
                                                  float* __restrict__ out)
{
    extern __shared__ float sm[];
    float* Bs = sm;                  // 128 x 130  (W_out)
    float* As = sm + 128*W_PAD;      // 128 x 68   (heads tile)

    const int b   = blockIdx.y;
    const int g0  = blockIdx.x * OT_GT;
    const int tid = threadIdx.x;

    {   // stage W_out: 128x128, rows padded to 130
        const float2* src = (const float2*)Wo;
        for (int i = tid; i < 128*64; i += 256) {
            int r = i >> 6, c = i & 63;
            *(float2*)(Bs + r*W_PAD + 2*c) = src[i];
        }
    }
    {   // stage A tile: heads2[b][hv][g0..g0+63], rows padded to 68
        // (cols >= Gg in g_heads2 are never written; zero-init -> safe)
        for (int i = tid; i < 128*16; i += 256) {
            int r = i >> 4, c = i & 15;
            *(float4*)(As + r*A_PAD + 4*c) =
                *(const float4*)(g_heads2 + ((size_t)b*128 + r)*GPAD + g0 + 4*c);
        }
    }
    __syncthreads();

    const int elane = tid & 15;      // 8 e-columns: e = 2*elane + 32*j (u64 pairs)
    const int grow  = tid >> 4;      // 4 g-rows: g0 + grow*4 + gg

    u64 acc[4][4];
#pragma unroll
    for (int gg = 0; gg < 4; gg++)
#pragma unroll
        for (int j = 0; j < 4; j++) acc[gg][j] = 0ull;

    const float4* Ap = (const float4*)(As + 4*grow);   // stride A_PAD/4 float4

#pragma unroll 4
    for (int hv = 0; hv < 128; hv++) {
        float4 av = Ap[hv*(A_PAD/4)];
        u64 aa[4];
        aa[0] = dup2(av.x); aa[1] = dup2(av.y);
        aa[2] = dup2(av.z); aa[3] = dup2(av.w);
        const u64* br = (const u64*)(Bs + hv*W_PAD) + elane;
#pragma unroll
        for (int j = 0; j < 4; j++) {
            u64 bv = br[16*j];
#pragma unroll
            for (int gg = 0; gg < 4; gg++)
                acc[gg][j] = fma2(bv, aa[gg], acc[gg][j]);
        }
    }

#pragma unroll
    for (int gg = 0; gg < 4; gg++) {
        const int g = g0 + grow*4 + gg;
        if (g < Gg) {
            float* op = out + ((size_t)b*Gg + g)*Ee;
#pragma unroll
            for (int j = 0; j < 4; j++) {
                float x, y; upk(acc[gg][j], x, y);
                *(float2*)(op + 2*elane + 32*j) = make_float2(x, y);
            }
        }
    }
}

// ==========================================================================
extern "C" void kernel_launch(void* const* d_in, const int* in_sizes, int n_in,
                              void* d_out, int out_size)
{
    const float* q  = (const float*)d_in[0];
    const float* Wq = (const float*)d_in[1];
    const float* Wk = (const float*)d_in[2];
    const float* Wv = (const float*)d_in[3];
    const float* W1 = (const float*)d_in[4];
    const float* W2 = (const float*)d_in[5];
    const float* W3 = (const float*)d_in[6];
    const float* W4 = (const float*)d_in[7];
    const float* Wo = (const float*)d_in[8];
    float* out = (float*)d_out;

    cudaFuncSetAttribute(proj_kernel, cudaFuncAttributeMaxDynamicSharedMemorySize, K1_SMEM);
    cudaFuncSetAttribute(attn_kernel, cudaFuncAttributeMaxDynamicSharedMemorySize, K2_SMEM);
    cudaFuncSetAttribute(out_kernel,  cudaFuncAttributeMaxDynamicSharedMemorySize, K3_SMEM);

    dim3 g0(7, Hh);
    wprep_kernel<<<g0, 256>>>(Wq, Wk, Wv, W1, W2, W3, W4);

    dim3 g1((NTOK + PT_TOK - 1)/PT_TOK, Hh);        // (101, 8)
    proj_kernel<<<g1, 256, K1_SMEM>>>(q);

    dim3 g2(Bb, Hh);                                // (16, 8) x 512 threads
    attn_kernel<<<g2, 512, K2_SMEM>>>();

    dim3 g3((Gg + OT_GT - 1)/OT_GT, Bb);            // (8, 16)
    out_kernel<<<g3, 256, K3_SMEM>>>(Wo, out);
}